// round 6
// baseline (speedup 1.0000x reference)
#include <cuda_runtime.h>
#include <cstdint>

// Dims (from reference): B=8, N=4096 -> M=32768; D=1024; E=512; C=4096
#define M_ROWS 32768
#define D_DIM  1024
#define E_DIM  512
#define C_DIM  4096

#define X_ELEMS  (M_ROWS * D_DIM)   // 33554432
#define RP_ELEMS (D_DIM * E_DIM)    // 524288
#define CB_ELEMS (C_DIM * E_DIM)    // 2097152

// Scratch (device global: allocation-free per harness rules).
__device__ float g_proj[(size_t)M_ROWS * E_DIM];  // 64 MB

// ---------- kernel 1: proj = x[M,1024] @ RP[1024,512] ----------
// 128x128 block tile, BK=16, 256 threads (tx=t&15, ty=t>>4).
// Thread owns rows {ty + i*16} and cols {tx + j*16} (bank-conflict-free).
__global__ __launch_bounds__(256) void proj_gemm(const float* __restrict__ A,
                                                 const float* __restrict__ B) {
    __shared__ float As[16][128];   // As[k][m]
    __shared__ float Bs[16][128];   // Bs[k][n]
    const int tid = threadIdx.x;
    const int tx = tid & 15;
    const int ty = tid >> 4;
    const int row0 = blockIdx.y * 128;
    const int col0 = blockIdx.x * 128;

    float acc[8][8];
    #pragma unroll
    for (int i = 0; i < 8; i++)
        #pragma unroll
        for (int j = 0; j < 8; j++) acc[i][j] = 0.f;

    for (int kt = 0; kt < D_DIM; kt += 16) {
        #pragma unroll
        for (int r = 0; r < 8; r++) {
            int idx = tid + r * 256;        // 0..2047
            int m   = idx >> 4;             // 0..127
            int kk  = idx & 15;             // 0..15
            As[kk][m] = A[(size_t)(row0 + m) * D_DIM + kt + kk];
        }
        #pragma unroll
        for (int r = 0; r < 8; r++) {
            int idx = tid + r * 256;
            int kk  = idx >> 7;             // 0..15
            int n   = idx & 127;            // 0..127
            Bs[kk][n] = B[(size_t)(kt + kk) * E_DIM + col0 + n];
        }
        __syncthreads();

        #pragma unroll
        for (int k = 0; k < 16; k++) {
            float a[8], b[8];
            #pragma unroll
            for (int i = 0; i < 8; i++) a[i] = As[k][ty + i * 16];
            #pragma unroll
            for (int j = 0; j < 8; j++) b[j] = Bs[k][tx + j * 16];
            #pragma unroll
            for (int i = 0; i < 8; i++)
                #pragma unroll
                for (int j = 0; j < 8; j++)
                    acc[i][j] += a[i] * b[j];
        }
        __syncthreads();
    }

    #pragma unroll
    for (int i = 0; i < 8; i++) {
        float* pr = g_proj + (size_t)(row0 + ty + i * 16) * E_DIM + col0;
        #pragma unroll
        for (int j = 0; j < 8; j++)
            pr[tx + j * 16] = acc[i][j];
    }
}

// ---------- kernel 2: fused scores + codebook norms + argmax ----------
// One block per 128 rows; 32 C-tiles of 128 codes, K=512 in BK=16 steps.
// Codebook inverse norms fused (nsum[j] accumulates b^2 along K).
// OUTPUT IS WRITTEN AS FLOAT32 (the harness reads d_out as float32;
// int writes are denormals == 0.0 -> the exactly-1.0 failures of R1-R5).
__global__ __launch_bounds__(256) void score_argmax(const float* __restrict__ cb,
                                                    float* __restrict__ out) {
    __shared__ float As[16][128];            // As[k][m]  (proj rows)
    __shared__ float Bs[16][128];            // Bs[k][n]  (codebook rows)
    __shared__ float sbest[16][8][16];       // [ty][i][tx]
    __shared__ int   sidx[16][8][16];

    const int tid = threadIdx.x;
    const int tx = tid & 15;
    const int ty = tid >> 4;
    const int row0 = blockIdx.x * 128;

    float best[8];
    int   besti[8];
    #pragma unroll
    for (int i = 0; i < 8; i++) { best[i] = -3.402823466e38f; besti[i] = 0; }

    for (int ct = 0; ct < C_DIM / 128; ct++) {
        float acc[8][8];
        float nsum[8];
        #pragma unroll
        for (int i = 0; i < 8; i++)
            #pragma unroll
            for (int j = 0; j < 8; j++) acc[i][j] = 0.f;
        #pragma unroll
        for (int j = 0; j < 8; j++) nsum[j] = 0.f;

        for (int kt = 0; kt < E_DIM; kt += 16) {
            #pragma unroll
            for (int r = 0; r < 8; r++) {
                int idx = tid + r * 256;
                int m   = idx >> 4;
                int kk  = idx & 15;
                As[kk][m] = g_proj[(size_t)(row0 + m) * E_DIM + kt + kk];
            }
            #pragma unroll
            for (int r = 0; r < 8; r++) {
                int idx = tid + r * 256;
                int n   = idx >> 4;
                int kk  = idx & 15;
                Bs[kk][n] = cb[(size_t)(ct * 128 + n) * E_DIM + kt + kk];
            }
            __syncthreads();

            #pragma unroll
            for (int k = 0; k < 16; k++) {
                float a[8], b[8];
                #pragma unroll
                for (int i = 0; i < 8; i++) a[i] = As[k][ty + i * 16];
                #pragma unroll
                for (int j = 0; j < 8; j++) b[j] = Bs[k][tx + j * 16];
                #pragma unroll
                for (int j = 0; j < 8; j++) nsum[j] += b[j] * b[j];
                #pragma unroll
                for (int i = 0; i < 8; i++)
                    #pragma unroll
                    for (int j = 0; j < 8; j++)
                        acc[i][j] += a[i] * b[j];
            }
            __syncthreads();
        }

        // running argmax update, scaling by the code's inverse norm.
        // Within a thread, c ascends across j and ct; strict > keeps the
        // FIRST max index (jnp.argmax tie-break).
        #pragma unroll
        for (int j = 0; j < 8; j++) {
            const int c = ct * 128 + tx + j * 16;
            const float iv = 1.f / fmaxf(sqrtf(nsum[j]), 1e-12f);
            #pragma unroll
            for (int i = 0; i < 8; i++) {
                float s = acc[i][j] * iv;
                if (s > best[i]) { best[i] = s; besti[i] = c; }
            }
        }
    }

    // cross-thread reduction: local row = ty + i*16; 16 tx lanes per row.
    #pragma unroll
    for (int i = 0; i < 8; i++) {
        sbest[ty][i][tx] = best[i];
        sidx[ty][i][tx]  = besti[i];
    }
    __syncthreads();

    if (tid < 128) {
        const int row = tid;                 // local row 0..127
        const int yy = row & 15;             // = ty
        const int ii = row >> 4;             // = i
        float bs = sbest[yy][ii][0];
        int   bi = sidx[yy][ii][0];
        #pragma unroll
        for (int t = 1; t < 16; t++) {
            float s  = sbest[yy][ii][t];
            int   id = sidx[yy][ii][t];
            if (s > bs || (s == bs && id < bi)) { bs = s; bi = id; }
        }
        // Float sentinels -> distinguishable rel_err levels if still broken:
        //   NaN scores   -> 1024.0 everywhere -> rel_err ~ 0.66
        //   zero scores  -> 2048.0 everywhere -> rel_err ~ 0.50
        float val = (float)bi;
        if (bs < -1e38f)      val = 1024.0f;
        else if (bs == 0.0f)  val = 2048.0f;
        out[row0 + row] = val;
    }
}

extern "C" void kernel_launch(void* const* d_in, const int* in_sizes, int n_in,
                              void* d_out, int out_size) {
    // Identify inputs by UNIQUE element counts, with positional fallback.
    const float* x  = nullptr;
    const float* rp = nullptr;
    const float* cb = nullptr;
    for (int i = 0; i < n_in; i++) {
        if (in_sizes[i] == X_ELEMS)       x  = (const float*)d_in[i];
        else if (in_sizes[i] == RP_ELEMS) rp = (const float*)d_in[i];
        else if (in_sizes[i] == CB_ELEMS) cb = (const float*)d_in[i];
    }
    if (!x || !rp || !cb) {
        x  = (const float*)d_in[0];
        rp = (const float*)d_in[1];
        cb = (const float*)d_in[2];
    }
    float* out = (float*)d_out;  // harness reads output as float32

    proj_gemm<<<dim3(E_DIM / 128, M_ROWS / 128), 256>>>(x, rp);
    score_argmax<<<M_ROWS / 128, 256>>>(cb, out);
}

// round 7
// speedup vs baseline: 1.2214x; 1.2214x over previous
#include <cuda_runtime.h>
#include <cstdint>

// Dims (fixed): B=8, N=4096 -> M=32768; D=1024; E=512; C=4096
#define M_ROWS 32768
#define D_DIM  1024
#define E_DIM  512
#define C_DIM  4096

#define X_ELEMS  (M_ROWS * D_DIM)   // 33554432
#define RP_ELEMS (D_DIM * E_DIM)    // 524288
#define CB_ELEMS (C_DIM * E_DIM)    // 2097152

// Scratch (device globals: allocation-free per harness rules).
__device__ float g_proj[(size_t)M_ROWS * E_DIM];  // 64 MB
__device__ float g_cbinv[C_DIM];                  // 16 KB

// ---------- packed f32x2 helpers (FFMA2: 2 fp32 FMAs / instruction) ----------
__device__ __forceinline__ unsigned long long pk2(float x, float y) {
    unsigned long long r;
    asm("mov.b64 %0, {%1, %2};" : "=l"(r) : "f"(x), "f"(y));
    return r;
}
__device__ __forceinline__ unsigned long long ffma2(unsigned long long a,
                                                    unsigned long long b,
                                                    unsigned long long c) {
    unsigned long long d;
    asm("fma.rn.f32x2 %0, %1, %2, %3;" : "=l"(d) : "l"(a), "l"(b), "l"(c));
    return d;
}
__device__ __forceinline__ void upk2(unsigned long long v, float& x, float& y) {
    asm("mov.b64 {%0, %1}, %2;" : "=f"(x), "=f"(y) : "l"(v));
}

// ---------- kernel 0: codebook row inverse L2 norms (warp per row) ----------
__global__ void codebook_invnorm(const float* __restrict__ cb) {
    const int row  = blockIdx.x * 8 + (threadIdx.x >> 5);
    const int lane = threadIdx.x & 31;
    if (row >= C_DIM) return;
    const float* v = cb + (size_t)row * E_DIM;
    float s = 0.f;
    #pragma unroll
    for (int q = 0; q < E_DIM / 32; q++) {
        float t = v[lane + q * 32];
        s += t * t;
    }
    #pragma unroll
    for (int o = 16; o > 0; o >>= 1) s += __shfl_xor_sync(0xffffffffu, s, o);
    if (lane == 0) g_cbinv[row] = 1.f / fmaxf(sqrtf(s), 1e-12f);
}

// Microtile mapping (256 threads, 128x128 tile):
//   tx = tid & 15 -> cols {tx*4+j, 64+tx*4+j}, j=0..3
//   ty = tid >> 4 -> rows {ty*4+i, 64+ty*4+i}, i=0..3
// Row pairs rp=0..3: rows ( (rp>>1)*64 + ty*4 + (rp&1)*2 ) + {0,1}

// ---------- kernel 1: proj = x[M,1024] @ RP[1024,512] ----------
__global__ __launch_bounds__(256) void proj_gemm(const float* __restrict__ A,
                                                 const float* __restrict__ B) {
    __shared__ __align__(16) float As[16][128];   // As[k][m]
    __shared__ __align__(16) float Bs[16][128];   // Bs[k][n]
    const int tid = threadIdx.x;
    const int tx = tid & 15;
    const int ty = tid >> 4;
    const int row0 = blockIdx.y * 128;
    const int col0 = blockIdx.x * 128;

    unsigned long long acc[4][8];
    #pragma unroll
    for (int rp = 0; rp < 4; rp++)
        #pragma unroll
        for (int j = 0; j < 8; j++) acc[rp][j] = 0ull;

    for (int kt = 0; kt < D_DIM; kt += 16) {
        #pragma unroll
        for (int r = 0; r < 8; r++) {
            int idx = tid + r * 256;        // 0..2047
            int m   = idx >> 4;
            int kk  = idx & 15;
            As[kk][m] = A[(size_t)(row0 + m) * D_DIM + kt + kk];
        }
        #pragma unroll
        for (int r = 0; r < 8; r++) {
            int idx = tid + r * 256;
            int kk  = idx >> 7;
            int n   = idx & 127;
            Bs[kk][n] = B[(size_t)(kt + kk) * E_DIM + col0 + n];
        }
        __syncthreads();

        #pragma unroll
        for (int k = 0; k < 16; k++) {
            const float4 a0 = *(const float4*)&As[k][ty * 4];
            const float4 a1 = *(const float4*)&As[k][64 + ty * 4];
            const float4 b0 = *(const float4*)&Bs[k][tx * 4];
            const float4 b1 = *(const float4*)&Bs[k][64 + tx * 4];
            unsigned long long av[4] = { pk2(a0.x, a0.y), pk2(a0.z, a0.w),
                                         pk2(a1.x, a1.y), pk2(a1.z, a1.w) };
            const float bsv[8] = { b0.x, b0.y, b0.z, b0.w, b1.x, b1.y, b1.z, b1.w };
            unsigned long long bb[8];
            #pragma unroll
            for (int j = 0; j < 8; j++) bb[j] = pk2(bsv[j], bsv[j]);
            #pragma unroll
            for (int rp = 0; rp < 4; rp++)
                #pragma unroll
                for (int j = 0; j < 8; j++)
                    acc[rp][j] = ffma2(av[rp], bb[j], acc[rp][j]);
        }
        __syncthreads();
    }

    // store: rp row pair = (rp>>1)*64 + ty*4 + (rp&1)*2 + {0,1}
    #pragma unroll
    for (int rp = 0; rp < 4; rp++) {
        const int r0 = (rp >> 1) * 64 + ty * 4 + (rp & 1) * 2;
        float lo[8], hi[8];
        #pragma unroll
        for (int j = 0; j < 8; j++) upk2(acc[rp][j], lo[j], hi[j]);
        float* p0 = g_proj + (size_t)(row0 + r0) * E_DIM + col0;
        float* p1 = p0 + E_DIM;
        *(float4*)(p0 + tx * 4)      = make_float4(lo[0], lo[1], lo[2], lo[3]);
        *(float4*)(p0 + 64 + tx * 4) = make_float4(lo[4], lo[5], lo[6], lo[7]);
        *(float4*)(p1 + tx * 4)      = make_float4(hi[0], hi[1], hi[2], hi[3]);
        *(float4*)(p1 + 64 + tx * 4) = make_float4(hi[4], hi[5], hi[6], hi[7]);
    }
}

// ---------- kernel 2: fused scores = proj @ cb^T * inv_norm + argmax ----------
__global__ __launch_bounds__(256) void score_argmax(const float* __restrict__ cb,
                                                    float* __restrict__ out) {
    __shared__ __align__(16) float As[16][128];
    __shared__ __align__(16) float Bs[16][128];
    __shared__ float sbest[128][17];   // padded: conflict-free epilogue
    __shared__ int   sidx[128][17];

    const int tid = threadIdx.x;
    const int tx = tid & 15;
    const int ty = tid >> 4;
    const int row0 = blockIdx.x * 128;

    float best[8];   // local rows: idx = rp*2 + h
    int   besti[8];
    #pragma unroll
    for (int i = 0; i < 8; i++) { best[i] = -3.402823466e38f; besti[i] = 0; }

    for (int ct = 0; ct < C_DIM / 128; ct++) {
        unsigned long long acc[4][8];
        #pragma unroll
        for (int rp = 0; rp < 4; rp++)
            #pragma unroll
            for (int j = 0; j < 8; j++) acc[rp][j] = 0ull;

        for (int kt = 0; kt < E_DIM; kt += 16) {
            #pragma unroll
            for (int r = 0; r < 8; r++) {
                int idx = tid + r * 256;
                int m   = idx >> 4;
                int kk  = idx & 15;
                As[kk][m] = g_proj[(size_t)(row0 + m) * E_DIM + kt + kk];
            }
            #pragma unroll
            for (int r = 0; r < 8; r++) {
                int idx = tid + r * 256;
                int n   = idx >> 4;
                int kk  = idx & 15;
                Bs[kk][n] = cb[(size_t)(ct * 128 + n) * E_DIM + kt + kk];
            }
            __syncthreads();

            #pragma unroll
            for (int k = 0; k < 16; k++) {
                const float4 a0 = *(const float4*)&As[k][ty * 4];
                const float4 a1 = *(const float4*)&As[k][64 + ty * 4];
                const float4 b0 = *(const float4*)&Bs[k][tx * 4];
                const float4 b1 = *(const float4*)&Bs[k][64 + tx * 4];
                unsigned long long av[4] = { pk2(a0.x, a0.y), pk2(a0.z, a0.w),
                                             pk2(a1.x, a1.y), pk2(a1.z, a1.w) };
                const float bsv[8] = { b0.x, b0.y, b0.z, b0.w, b1.x, b1.y, b1.z, b1.w };
                unsigned long long bb[8];
                #pragma unroll
                for (int j = 0; j < 8; j++) bb[j] = pk2(bsv[j], bsv[j]);
                #pragma unroll
                for (int rp = 0; rp < 4; rp++)
                    #pragma unroll
                    for (int j = 0; j < 8; j++)
                        acc[rp][j] = ffma2(av[rp], bb[j], acc[rp][j]);
            }
            __syncthreads();
        }

        // argmax update. Per thread, c ascends across j (cols tx*4..+3 then
        // 64+tx*4..+3) and across ct; strict > keeps FIRST max (jnp.argmax).
        #pragma unroll
        for (int j = 0; j < 8; j++) {
            const int col = (j < 4) ? (tx * 4 + j) : (64 + tx * 4 + (j - 4));
            const int c   = ct * 128 + col;
            const float iv = g_cbinv[c];
            #pragma unroll
            for (int rp = 0; rp < 4; rp++) {
                float s0, s1;
                upk2(acc[rp][j], s0, s1);
                s0 *= iv; s1 *= iv;
                if (s0 > best[rp * 2 + 0]) { best[rp * 2 + 0] = s0; besti[rp * 2 + 0] = c; }
                if (s1 > best[rp * 2 + 1]) { best[rp * 2 + 1] = s1; besti[rp * 2 + 1] = c; }
            }
        }
    }

    // cross-thread reduction: local row = (rp>>1)*64 + ty*4 + (rp&1)*2 + h
    #pragma unroll
    for (int rp = 0; rp < 4; rp++) {
        #pragma unroll
        for (int h = 0; h < 2; h++) {
            const int lrow = (rp >> 1) * 64 + ty * 4 + (rp & 1) * 2 + h;
            sbest[lrow][tx] = best[rp * 2 + h];
            sidx[lrow][tx]  = besti[rp * 2 + h];
        }
    }
    __syncthreads();

    if (tid < 128) {
        const int row = tid;
        float bs = sbest[row][0];
        int   bi = sidx[row][0];
        #pragma unroll
        for (int t = 1; t < 16; t++) {
            float s  = sbest[row][t];
            int   id = sidx[row][t];
            if (s > bs || (s == bs && id < bi)) { bs = s; bi = id; }
        }
        out[row0 + row] = (float)bi;   // harness reads output as float32
    }
}

extern "C" void kernel_launch(void* const* d_in, const int* in_sizes, int n_in,
                              void* d_out, int out_size) {
    const float* x  = nullptr;
    const float* rp = nullptr;
    const float* cb = nullptr;
    for (int i = 0; i < n_in; i++) {
        if (in_sizes[i] == X_ELEMS)       x  = (const float*)d_in[i];
        else if (in_sizes[i] == RP_ELEMS) rp = (const float*)d_in[i];
        else if (in_sizes[i] == CB_ELEMS) cb = (const float*)d_in[i];
    }
    if (!x || !rp || !cb) {
        x  = (const float*)d_in[0];
        rp = (const float*)d_in[1];
        cb = (const float*)d_in[2];
    }
    float* out = (float*)d_out;  // harness reads output as float32

    codebook_invnorm<<<C_DIM / 8, 256>>>(cb);
    proj_gemm<<<dim3(E_DIM / 128, M_ROWS / 128), 256>>>(x, rp);
    score_argmax<<<M_ROWS / 128, 256>>>(cb, out);
}

// round 8
// speedup vs baseline: 1.5575x; 1.2752x over previous
#include <cuda_runtime.h>
#include <cstdint>

// Dims (fixed): B=8, N=4096 -> M=32768; D=1024; E=512; C=4096
#define M_ROWS 32768
#define D_DIM  1024
#define E_DIM  512
#define C_DIM  4096

#define X_ELEMS  (M_ROWS * D_DIM)   // 33554432
#define RP_ELEMS (D_DIM * E_DIM)    // 524288
#define CB_ELEMS (C_DIM * E_DIM)    // 2097152

// Scratch (device globals: allocation-free per harness rules).
__device__ __align__(256) float g_projT[(size_t)E_DIM * M_ROWS];  // proj^T [E][M], 64 MB
__device__ __align__(256) float g_cbT[(size_t)E_DIM * C_DIM];     // cb^T  [E][C],  8 MB
__device__ __align__(256) float g_cbinv[C_DIM];                   // 16 KB

// ---------- packed f32x2 helpers ----------
__device__ __forceinline__ unsigned long long ffma2(unsigned long long a,
                                                    unsigned long long b,
                                                    unsigned long long c) {
    unsigned long long d;
    asm("fma.rn.f32x2 %0, %1, %2, %3;" : "=l"(d) : "l"(a), "l"(b), "l"(c));
    return d;
}
__device__ __forceinline__ void upk2(unsigned long long v, float& x, float& y) {
    asm("mov.b64 {%0, %1}, %2;" : "=f"(x), "=f"(y) : "l"(v));
}
// 128B-block XOR swizzle on 16B chunks: conflict-free strided LDS.128.
__device__ __host__ __forceinline__ constexpr int swz(int c) { return c ^ ((c >> 3) & 7); }

// ---------- kernel 0a: codebook row inverse L2 norms (warp per row) ----------
__global__ void codebook_invnorm(const float* __restrict__ cb) {
    const int row  = blockIdx.x * 8 + (threadIdx.x >> 5);
    const int lane = threadIdx.x & 31;
    if (row >= C_DIM) return;
    const float* v = cb + (size_t)row * E_DIM;
    float s = 0.f;
    #pragma unroll
    for (int q = 0; q < E_DIM / 32; q++) {
        float t = v[lane + q * 32];
        s += t * t;
    }
    #pragma unroll
    for (int o = 16; o > 0; o >>= 1) s += __shfl_xor_sync(0xffffffffu, s, o);
    if (lane == 0) g_cbinv[row] = 1.f / fmaxf(sqrtf(s), 1e-12f);
}

// ---------- kernel 0b: transpose codebook [C,E] -> g_cbT [E,C] ----------
__global__ void cb_transpose(const float* __restrict__ cb) {
    __shared__ float t[32][33];
    const int tx = threadIdx.x, ty = threadIdx.y;       // 32 x 8
    const int c0 = blockIdx.x * 32, e0 = blockIdx.y * 32;
    #pragma unroll
    for (int i = 0; i < 4; i++)
        t[ty + 8 * i][tx] = cb[(size_t)(c0 + ty + 8 * i) * E_DIM + e0 + tx];
    __syncthreads();
    #pragma unroll
    for (int i = 0; i < 4; i++)
        g_cbT[(size_t)(e0 + ty + 8 * i) * C_DIM + c0 + tx] = t[tx][ty + 8 * i];
}

// Microtile (256 thr, 128x128 tile): tx=tid&15 -> cols {4tx+j, 64+4tx+j};
// ty=tid>>4 -> rows {4ty+i, 64+4ty+i}. acc[rp][j]: row pairs
// rp0=(4ty,4ty+1) rp1=(4ty+2,4ty+3) rp2=(64+4ty,64+4ty+1) rp3=(64+4ty+2,+3).

// ---------- kernel 1: proj^T = (x[M,1024] @ RP[1024,512])^T ----------
__global__ __launch_bounds__(256) void proj_gemm(const float* __restrict__ X,
                                                 const float* __restrict__ RP) {
    __shared__ float As[2][16][128];   // [k][m]
    __shared__ float Bs[2][16][256];   // [k][dup-col], swizzled
    const int tid = threadIdx.x;
    const int tx = tid & 15;
    const int ty = tid >> 4;
    const int row0 = blockIdx.y * 128;
    const int col0 = blockIdx.x * 128;

    const int o0 = 4 * swz(2 * tx), o1 = 4 * swz(2 * tx + 1);
    const int o2 = 4 * swz(32 + 2 * tx), o3 = 4 * swz(33 + 2 * tx);

    unsigned long long acc[4][8];
    #pragma unroll
    for (int r = 0; r < 4; r++)
        #pragma unroll
        for (int j = 0; j < 8; j++) acc[r][j] = 0ull;

    auto ldA = [&](int r, int kt) {
        int idx = tid + 256 * r, m = idx >> 2, k4 = (idx & 3) * 4;
        return *(const float4*)(X + (size_t)(row0 + m) * D_DIM + kt + k4);
    };
    auto stA = [&](int b, int r, float4 v) {
        int idx = tid + 256 * r, m = idx >> 2, k4 = (idx & 3) * 4;
        As[b][k4 + 0][m] = v.x; As[b][k4 + 1][m] = v.y;
        As[b][k4 + 2][m] = v.z; As[b][k4 + 3][m] = v.w;
    };
    auto ldB = [&](int r, int kt) {
        int idx = tid + 256 * r, n4 = (idx & 31) * 4, kb = idx >> 5;
        return *(const float4*)(RP + (size_t)(kt + kb) * E_DIM + col0 + n4);
    };
    auto stB = [&](int b, int r, float4 v) {
        int idx = tid + 256 * r, cB = (idx & 31) * 2, kb = idx >> 5;
        float* br = Bs[b][kb];
        *(float4*)(br + 4 * swz(cB))     = make_float4(v.x, v.x, v.y, v.y);
        *(float4*)(br + 4 * swz(cB + 1)) = make_float4(v.z, v.z, v.w, v.w);
    };

    stA(0, 0, ldA(0, 0)); stA(0, 1, ldA(1, 0));
    stB(0, 0, ldB(0, 0)); stB(0, 1, ldB(1, 0));
    __syncthreads();

    const int STEPS = D_DIM / 16;   // 64
    for (int s = 0; s < STEPS; s++) {
        const int buf = s & 1;
        const bool pf = (s + 1 < STEPS);
        float4 pa0, pa1, pb0, pb1;
        if (pf) {
            int kt1 = (s + 1) * 16;
            pa0 = ldA(0, kt1); pa1 = ldA(1, kt1);
            pb0 = ldB(0, kt1); pb1 = ldB(1, kt1);
        }
        #pragma unroll
        for (int k = 0; k < 16; k++) {
            ulonglong2 apA = *(const ulonglong2*)&As[buf][k][4 * ty];
            ulonglong2 apB = *(const ulonglong2*)&As[buf][k][64 + 4 * ty];
            const float* br = Bs[buf][k];
            ulonglong2 b0 = *(const ulonglong2*)(br + o0);
            ulonglong2 b1 = *(const ulonglong2*)(br + o1);
            ulonglong2 b2 = *(const ulonglong2*)(br + o2);
            ulonglong2 b3 = *(const ulonglong2*)(br + o3);
            unsigned long long av[4] = { apA.x, apA.y, apB.x, apB.y };
            unsigned long long bb[8] = { b0.x, b0.y, b1.x, b1.y,
                                         b2.x, b2.y, b3.x, b3.y };
            #pragma unroll
            for (int r = 0; r < 4; r++)
                #pragma unroll
                for (int j = 0; j < 8; j++)
                    acc[r][j] = ffma2(av[r], bb[j], acc[r][j]);
        }
        if (pf) {
            int nb = buf ^ 1;
            stA(nb, 0, pa0); stA(nb, 1, pa1);
            stB(nb, 0, pb0); stB(nb, 1, pb1);
        }
        __syncthreads();
    }

    // epilogue: write transposed projections
    #pragma unroll
    for (int j = 0; j < 8; j++) {
        const int col = col0 + ((j < 4) ? (4 * tx + j) : (60 + 4 * tx + j));
        float v0, v1, v2, v3;
        upk2(acc[0][j], v0, v1); upk2(acc[1][j], v2, v3);
        *(float4*)(g_projT + (size_t)col * M_ROWS + row0 + 4 * ty)
            = make_float4(v0, v1, v2, v3);
        upk2(acc[2][j], v0, v1); upk2(acc[3][j], v2, v3);
        *(float4*)(g_projT + (size_t)col * M_ROWS + row0 + 64 + 4 * ty)
            = make_float4(v0, v1, v2, v3);
    }
}

// ---------- kernel 2: fused scores = projT^T @ cbT * inv_norm + argmax ----------
__global__ __launch_bounds__(256) void score_argmax(float* __restrict__ out) {
    __shared__ float As[2][16][128];
    __shared__ float Bs[2][16][256];
    const int tid = threadIdx.x;
    const int tx = tid & 15;
    const int ty = tid >> 4;
    const int row0 = blockIdx.x * 128;

    const int o0 = 4 * swz(2 * tx), o1 = 4 * swz(2 * tx + 1);
    const int o2 = 4 * swz(32 + 2 * tx), o3 = 4 * swz(33 + 2 * tx);

    unsigned long long acc[4][8];
    #pragma unroll
    for (int r = 0; r < 4; r++)
        #pragma unroll
        for (int j = 0; j < 8; j++) acc[r][j] = 0ull;

    float best[8];
    int   besti[8];
    #pragma unroll
    for (int i = 0; i < 8; i++) { best[i] = -3.402823466e38f; besti[i] = 0; }

    auto ldA = [&](int r, int kt) {
        int idx = tid + 256 * r, m4 = (idx & 31) * 4, ka = idx >> 5;
        return *(const float4*)(g_projT + (size_t)(kt + ka) * M_ROWS + row0 + m4);
    };
    auto stA = [&](int b, int r, float4 v) {
        int idx = tid + 256 * r, m4 = (idx & 31) * 4, ka = idx >> 5;
        *(float4*)&As[b][ka][m4] = v;
    };
    auto ldB = [&](int r, int ct, int kt) {
        int idx = tid + 256 * r, n4 = (idx & 31) * 4, kb = idx >> 5;
        return *(const float4*)(g_cbT + (size_t)(kt + kb) * C_DIM + ct + n4);
    };
    auto stB = [&](int b, int r, float4 v) {
        int idx = tid + 256 * r, cB = (idx & 31) * 2, kb = idx >> 5;
        float* br = Bs[b][kb];
        *(float4*)(br + 4 * swz(cB))     = make_float4(v.x, v.x, v.y, v.y);
        *(float4*)(br + 4 * swz(cB + 1)) = make_float4(v.z, v.z, v.w, v.w);
    };

    stA(0, 0, ldA(0, 0)); stA(0, 1, ldA(1, 0));
    stB(0, 0, ldB(0, 0, 0)); stB(0, 1, ldB(1, 0, 0));
    __syncthreads();

    const int TOT = 32 * 32;   // 32 C-tiles x 32 K-tiles
    for (int s = 0; s < TOT; s++) {
        const int buf = s & 1;
        const bool pf = (s + 1 < TOT);
        float4 pa0, pa1, pb0, pb1;
        if (pf) {
            int kt1 = ((s + 1) & 31) * 16;
            int ct1 = ((s + 1) >> 5) * 128;
            pa0 = ldA(0, kt1); pa1 = ldA(1, kt1);
            pb0 = ldB(0, ct1, kt1); pb1 = ldB(1, ct1, kt1);
        }
        #pragma unroll
        for (int k = 0; k < 16; k++) {
            ulonglong2 apA = *(const ulonglong2*)&As[buf][k][4 * ty];
            ulonglong2 apB = *(const ulonglong2*)&As[buf][k][64 + 4 * ty];
            const float* br = Bs[buf][k];
            ulonglong2 b0 = *(const ulonglong2*)(br + o0);
            ulonglong2 b1 = *(const ulonglong2*)(br + o1);
            ulonglong2 b2 = *(const ulonglong2*)(br + o2);
            ulonglong2 b3 = *(const ulonglong2*)(br + o3);
            unsigned long long av[4] = { apA.x, apA.y, apB.x, apB.y };
            unsigned long long bb[8] = { b0.x, b0.y, b1.x, b1.y,
                                         b2.x, b2.y, b3.x, b3.y };
            #pragma unroll
            for (int r = 0; r < 4; r++)
                #pragma unroll
                for (int j = 0; j < 8; j++)
                    acc[r][j] = ffma2(av[r], bb[j], acc[r][j]);
        }
        if ((s & 31) == 31) {
            // end of a C-tile: argmax update (c ascending within thread ->
            // strict > keeps FIRST max, matching jnp.argmax), then reset acc.
            const int ctb = (s >> 5) * 128;
            #pragma unroll
            for (int j = 0; j < 8; j++) {
                const int c = ctb + ((j < 4) ? (4 * tx + j) : (60 + 4 * tx + j));
                const float ivn = g_cbinv[c];
                #pragma unroll
                for (int r = 0; r < 4; r++) {
                    float s0, s1;
                    upk2(acc[r][j], s0, s1);
                    s0 *= ivn; s1 *= ivn;
                    if (s0 > best[r * 2 + 0]) { best[r * 2 + 0] = s0; besti[r * 2 + 0] = c; }
                    if (s1 > best[r * 2 + 1]) { best[r * 2 + 1] = s1; besti[r * 2 + 1] = c; }
                    acc[r][j] = 0ull;
                }
            }
        }
        if (pf) {
            int nb = buf ^ 1;
            stA(nb, 0, pa0); stA(nb, 1, pa1);
            stB(nb, 0, pb0); stB(nb, 1, pb1);
        }
        __syncthreads();
    }

    // shuffle epilogue: reduce over the 16 tx lanes (half-warp, xor<16).
    #pragma unroll
    for (int e = 0; e < 8; e++) {
        float sv = best[e];
        int   ix = besti[e];
        #pragma unroll
        for (int off = 1; off <= 8; off <<= 1) {
            float ps = __shfl_xor_sync(0xffffffffu, sv, off);
            int   pi = __shfl_xor_sync(0xffffffffu, ix, off);
            if (ps > sv || (ps == sv && pi < ix)) { sv = ps; ix = pi; }
        }
        if (tx == 0) {
            const int rp = e >> 1;
            const int row = (rp >> 1) * 64 + 4 * ty + (rp & 1) * 2 + (e & 1);
            out[row0 + row] = (float)ix;   // harness reads output as float32
        }
    }
}

extern "C" void kernel_launch(void* const* d_in, const int* in_sizes, int n_in,
                              void* d_out, int out_size) {
    const float* x  = nullptr;
    const float* rp = nullptr;
    const float* cb = nullptr;
    for (int i = 0; i < n_in; i++) {
        if (in_sizes[i] == X_ELEMS)       x  = (const float*)d_in[i];
        else if (in_sizes[i] == RP_ELEMS) rp = (const float*)d_in[i];
        else if (in_sizes[i] == CB_ELEMS) cb = (const float*)d_in[i];
    }
    if (!x || !rp || !cb) {
        x  = (const float*)d_in[0];
        rp = (const float*)d_in[1];
        cb = (const float*)d_in[2];
    }
    float* out = (float*)d_out;  // harness reads output as float32

    codebook_invnorm<<<C_DIM / 8, 256>>>(cb);
    cb_transpose<<<dim3(C_DIM / 32, E_DIM / 32), dim3(32, 8)>>>(cb);
    proj_gemm<<<dim3(E_DIM / 128, M_ROWS / 128), 256>>>(x, rp);
    score_argmax<<<M_ROWS / 128, 256>>>(out);
}